// round 4
// baseline (speedup 1.0000x reference)
#include <cuda_runtime.h>
#include <cstddef>

#define BSZ 8
#define SEQLEN 2048
#define VOCAB 32000
#define BOS 1
#define V4 (VOCAB / 4)   // 8000 float4 per row

// Global scratch (allocation-free rule: __device__ globals only)
__device__ int g_hist[BSZ][VOCAB];   // 1 MB
__device__ int g_pred[BSZ];

// ---------------------------------------------------------------------------
// Kernel A: per-batch majority token.
// One block per batch row. Zero own histogram row, atomicAdd valid tokens,
// argmax with tie -> lowest index via key = (count<<15) | (32767 - v).
// __syncthreads() guarantees global-memory visibility within the block.
// ---------------------------------------------------------------------------
__global__ void majority_kernel(const int* __restrict__ ids) {
    const int b = blockIdx.x;
    const int t = threadIdx.x;
    const int nt = blockDim.x;
    int* __restrict__ hist = g_hist[b];

    // zero histogram row
    for (int v = t; v < VOCAB; v += nt) hist[v] = 0;
    __syncthreads();

    // accumulate valid tokens (exclude pad=0 and BOS=1)
    const int* row = ids + (size_t)b * SEQLEN;
    for (int s = t; s < SEQLEN; s += nt) {
        int tok = row[s];
        if (tok != 0 && tok != BOS) atomicAdd(&hist[tok], 1);
    }
    __syncthreads();

    // argmax with lowest-index tie-break
    __shared__ int best;
    if (t == 0) best = 0;
    __syncthreads();

    int lb = 0;
    for (int v = t; v < VOCAB; v += nt) {
        // count <= 2048 -> key < 2^26, fits signed int
        int key = (hist[v] << 15) | (32767 - v);
        if (key > lb) lb = key;
    }
    atomicMax(&best, lb);
    __syncthreads();

    if (t == 0) {
        int cnt = best >> 15;
        int v = 32767 - (best & 32767);
        g_pred[b] = (cnt > 0) ? v : BOS;  // no valid tokens -> BOS
    }
}

// ---------------------------------------------------------------------------
// Kernel B: streaming fill. grid = (SEQLEN, BSZ); each block writes one
// (b, s) row of VOCAB floats as 8000 float4 stores. One compare + SELs per
// 16 bytes -> pure HBM-write-bound.
// ---------------------------------------------------------------------------
__global__ void fill_kernel(float4* __restrict__ out) {
    const int b = blockIdx.y;
    const int s = blockIdx.x;

    const int p  = g_pred[b];
    const int p4 = p >> 2;   // float4 index holding the +6
    const int pc = p & 3;    // component within that float4

    float4 neg = make_float4(-6.0f, -6.0f, -6.0f, -6.0f);
    float4 special = neg;
    if      (pc == 0) special.x = 6.0f;
    else if (pc == 1) special.y = 6.0f;
    else if (pc == 2) special.z = 6.0f;
    else              special.w = 6.0f;

    float4* __restrict__ dst = out + ((size_t)b * SEQLEN + s) * V4;

    for (int i = threadIdx.x; i < V4; i += blockDim.x) {
        dst[i] = (i == p4) ? special : neg;
    }
}

extern "C" void kernel_launch(void* const* d_in, const int* in_sizes, int n_in,
                              void* d_out, int out_size) {
    (void)in_sizes; (void)n_in; (void)out_size;
    const int* ids = (const int*)d_in[0];
    float4* out = (float4*)d_out;

    majority_kernel<<<BSZ, 1024>>>(ids);
    fill_kernel<<<dim3(SEQLEN, BSZ), 256>>>(out);
}